// round 12
// baseline (speedup 1.0000x reference)
#include <cuda_runtime.h>
#include <cuda_bf16.h>
#include <math.h>

// Problem constants
#define BB 64        // batch
#define TT 512       // seq len
#define HH 1024      // hidden (= input size)
#define GG 4096      // 4*H gates
#define LL 3         // layers
#define NBLK 256     // persistent grid size (2/SM on 148 SMs -> all resident)

// ---------------- scratch (device globals; no allocation allowed) ----------------
__device__ float g_proj[(size_t)TT * BB * GG];   // [T][B][4H]  512 MB
__device__ float g_buf0[(size_t)BB * TT * HH];   // layer0 output  128 MB
__device__ float g_buf1[(size_t)BB * TT * HH];   // layer1 output  128 MB
__device__ float g_hA[BB * HH];
__device__ float g_hB[BB * HH];
__device__ float g_c[BB * HH];
__device__ unsigned int g_bar_arrive;            // zero-init; returns to 0 after each barrier
__device__ unsigned int g_bar_gen;               // monotonic across barriers/replays

#define FMA2(acc, x, w) \
    asm("fma.rn.f32x2 %0, %1, %2, %0;" : "+l"(acc) : "l"(x), "l"(w))

// ---------------- input-projection GEMM ----------------
// proj[t][b][g] = sum_k A[(b*T+t)][k] * W[g][k] + bih[g] + bhh[g]
// 128x128 block tile, BK=16, 256 threads, 8x8 micro-tile, f32x2-packed over j.
__global__ void __launch_bounds__(256) xproj_gemm(
    const float* __restrict__ A,
    const float* __restrict__ W,
    const float* __restrict__ bih,
    const float* __restrict__ bhh,
    float* __restrict__ proj)
{
    __shared__ float As[16][128];
    __shared__ float Bs[16][128];

    const int tid = threadIdx.x;
    const int bm = blockIdx.y * 128;
    const int bn = blockIdx.x * 128;
    const int tx = tid & 15;
    const int ty = tid >> 4;

    unsigned long long acc2[8][4];
#pragma unroll
    for (int i = 0; i < 8; i++)
#pragma unroll
        for (int j = 0; j < 4; j++) acc2[i][j] = 0ull;

    const int lr = tid >> 1;            // 0..127
    const int lc = (tid & 1) * 8;       // 0 or 8
    const float* Ap = A + (size_t)(bm + lr) * HH + lc;
    const float* Wp = W + (size_t)(bn + lr) * HH + lc;

    for (int k = 0; k < HH; k += 16) {
        float4 av0 = *(const float4*)(Ap + k);
        float4 av1 = *(const float4*)(Ap + k + 4);
        float4 wv0 = *(const float4*)(Wp + k);
        float4 wv1 = *(const float4*)(Wp + k + 4);
        __syncthreads();
        As[lc + 0][lr] = av0.x; As[lc + 1][lr] = av0.y;
        As[lc + 2][lr] = av0.z; As[lc + 3][lr] = av0.w;
        As[lc + 4][lr] = av1.x; As[lc + 5][lr] = av1.y;
        As[lc + 6][lr] = av1.z; As[lc + 7][lr] = av1.w;
        Bs[lc + 0][lr] = wv0.x; Bs[lc + 1][lr] = wv0.y;
        Bs[lc + 2][lr] = wv0.z; Bs[lc + 3][lr] = wv0.w;
        Bs[lc + 4][lr] = wv1.x; Bs[lc + 5][lr] = wv1.y;
        Bs[lc + 6][lr] = wv1.z; Bs[lc + 7][lr] = wv1.w;
        __syncthreads();
#pragma unroll
        for (int kk = 0; kk < 16; kk++) {
            float a[8];
            *(float4*)&a[0] = *(const float4*)&As[kk][ty * 8];
            *(float4*)&a[4] = *(const float4*)&As[kk][ty * 8 + 4];
            ulonglong2 b0 = *(const ulonglong2*)&Bs[kk][tx * 8];
            ulonglong2 b1 = *(const ulonglong2*)&Bs[kk][tx * 8 + 4];
#pragma unroll
            for (int i = 0; i < 8; i++) {
                unsigned long long a2;
                asm("mov.b64 %0, {%1, %1};" : "=l"(a2) : "f"(a[i]));
                FMA2(acc2[i][0], a2, b0.x);
                FMA2(acc2[i][1], a2, b0.y);
                FMA2(acc2[i][2], a2, b1.x);
                FMA2(acc2[i][3], a2, b1.y);
            }
        }
    }

#pragma unroll
    for (int i = 0; i < 8; i++) {
        int row = bm + ty * 8 + i;      // row = b*T + t
        int b   = row >> 9;
        int t   = row & 511;
        float* op = proj + ((size_t)(t * BB + b)) * GG + bn + tx * 8;
#pragma unroll
        for (int j2 = 0; j2 < 4; j2++) {
            float lo, hi;
            asm("mov.b64 {%0, %1}, %2;" : "=f"(lo), "=f"(hi) : "l"(acc2[i][j2]));
            int c0 = bn + tx * 8 + 2 * j2;
            op[2 * j2 + 0] = lo + bih[c0]     + bhh[c0];
            op[2 * j2 + 1] = hi + bih[c0 + 1] + bhh[c0 + 1];
        }
    }
}

// ---------------- persistent per-layer LSTM recurrence ----------------
// 256 blocks x 256 threads, ALL co-resident (launch_bounds(256,2), smem < 114KB/block).
// Block owns 4 h-columns; its 16x1024 Whh slice lives in smem for all 512 steps.
// Grid-wide sense-reversing barrier between timesteps (replay-safe: arrive
// self-resets, gen is monotonic).
__global__ void __launch_bounds__(256, 2) lstm_layer_persistent(
    const float* __restrict__ proj,     // [T][B][G]
    const float* __restrict__ Whh,      // [G][H]
    float* __restrict__ outseq,         // [B][T][H]
    float* __restrict__ hA,
    float* __restrict__ hB,
    float* __restrict__ cbuf)           // [B][H]
{
    __shared__ float wsa[16][1028];     // full weight slice, stride 1028 (bank period 8)
    __shared__ float hs[64][68];        // h chunk
    __shared__ float gsm[64][17];       // gate preactivations

    const int tid = threadIdx.x;
    const int n  = tid & 15;            // local gate col 0..15
    const int ty = tid >> 4;            // 0..15 -> 4 batch rows each
    const int j0 = blockIdx.x * 4;
    const int q  = n >> 2;
    const int jj = n & 3;
    const int gc = q * HH + j0 + jj;

    // ---- load this block's Whh slice into smem ONCE ----
    {
        int row  = tid >> 4;            // 0..15
        int c4   = tid & 15;            // 0..15
        int grow = (row >> 2) * HH + j0 + (row & 3);
        const float4* src = (const float4*)(Whh + (size_t)grow * HH);
#pragma unroll
        for (int c = 0; c < 16; c++) {
            int f4 = c * 16 + c4;       // 0..255 float4 index
            float4 v = src[f4];
            *(float4*)&wsa[row][f4 * 4] = v;
        }
    }
    __syncthreads();

    for (int t = 0; t < TT; t++) {
        unsigned long long acc2[4];
#pragma unroll
        for (int r = 0; r < 4; r++) {
            float p = proj[((size_t)t * BB + (ty * 4 + r)) * GG + gc];
            asm("mov.b64 %0, {%1, %2};" : "=l"(acc2[r]) : "f"(p), "f"(0.0f));
        }

        if (t > 0) {
            const float* hprev = (t & 1) ? hA : hB;
            for (int k0 = 0; k0 < HH; k0 += 64) {
#pragma unroll
                for (int it = 0; it < 4; it++) {
                    int idx = tid + it * 256;
                    int m  = idx >> 4;
                    int kq = idx & 15;
                    float4 v = *(const float4*)(hprev + (size_t)m * HH + k0 + kq * 4);
                    *(float4*)&hs[m][kq * 4] = v;
                }
                __syncthreads();
#pragma unroll 4
                for (int kk = 0; kk < 64; kk += 4) {
                    ulonglong2 w2 = *(const ulonglong2*)&wsa[n][k0 + kk];
#pragma unroll
                    for (int r = 0; r < 4; r++) {
                        ulonglong2 h2 = *(const ulonglong2*)&hs[ty * 4 + r][kk];
                        FMA2(acc2[r], h2.x, w2.x);
                        FMA2(acc2[r], h2.y, w2.y);
                    }
                }
                __syncthreads();
            }
        }

#pragma unroll
        for (int r = 0; r < 4; r++) {
            float lo, hi;
            asm("mov.b64 {%0, %1}, %2;" : "=f"(lo), "=f"(hi) : "l"(acc2[r]));
            gsm[ty * 4 + r][n] = lo + hi;
        }
        __syncthreads();

        float* hcur = (t & 1) ? hB : hA;
        {
            int m  = tid >> 2;
            int j2 = tid & 3;
            float ig = gsm[m][0  + j2];
            float fg = gsm[m][4  + j2];
            float gg = gsm[m][8  + j2];
            float og = gsm[m][12 + j2];
            ig = 1.f / (1.f + expf(-ig));
            fg = 1.f / (1.f + expf(-fg));
            og = 1.f / (1.f + expf(-og));
            gg = tanhf(gg);
            int j = j0 + j2;
            float cp = (t == 0) ? 0.f : cbuf[(size_t)m * HH + j];
            float c  = fg * cp + ig * gg;
            cbuf[(size_t)m * HH + j] = c;
            float h = og * tanhf(c);
            hcur[(size_t)m * HH + j] = h;
            outseq[((size_t)m * TT + t) * HH + j] = h;
        }

        // ---- grid-wide barrier between timesteps ----
        __syncthreads();            // all threads done (incl. smem reuse next iter)
        __threadfence();            // h/c writes visible device-wide
        if (tid == 0) {
            unsigned int gen = atomicAdd(&g_bar_gen, 0u);   // ordered read of gen
            __threadfence();
            unsigned int ticket = atomicAdd(&g_bar_arrive, 1u);
            if (ticket == (unsigned int)(gridDim.x - 1)) {
                g_bar_arrive = 0;                            // reset before release
                __threadfence();
                atomicAdd(&g_bar_gen, 1u);                   // release
            } else {
                while (*(volatile unsigned int*)&g_bar_gen == gen) {
                    __nanosleep(64);
                }
            }
            __threadfence();
        }
        __syncthreads();
    }
}

// ---------------- launch: 6 graph nodes total ----------------
extern "C" void kernel_launch(void* const* d_in, const int* in_sizes, int n_in,
                              void* d_out, int out_size)
{
    (void)in_sizes; (void)n_in; (void)out_size;
    const float* x   = (const float*)d_in[0];
    const float* Wih = (const float*)d_in[1];
    const float* Whh = (const float*)d_in[2];
    const float* bih = (const float*)d_in[3];
    const float* bhh = (const float*)d_in[4];
    float* out = (float*)d_out;

    float *proj, *buf0, *buf1, *hA, *hB, *cb;
    cudaGetSymbolAddress((void**)&proj, g_proj);
    cudaGetSymbolAddress((void**)&buf0, g_buf0);
    cudaGetSymbolAddress((void**)&buf1, g_buf1);
    cudaGetSymbolAddress((void**)&hA,   g_hA);
    cudaGetSymbolAddress((void**)&hB,   g_hB);
    cudaGetSymbolAddress((void**)&cb,   g_c);

    for (int l = 0; l < LL; l++) {
        const float* in_seq  = (l == 0) ? x    : ((l == 1) ? buf0 : buf1);
        float*       out_seq = (l == 0) ? buf0 : ((l == 1) ? buf1 : out);
        const float* Wih_l = Wih + (size_t)l * GG * HH;
        const float* Whh_l = Whh + (size_t)l * GG * HH;
        const float* bih_l = bih + (size_t)l * GG;
        const float* bhh_l = bhh + (size_t)l * GG;

        dim3 ggrid(GG / 128, (BB * TT) / 128);   // (32, 256)
        xproj_gemm<<<ggrid, 256>>>(in_seq, Wih_l, bih_l, bhh_l, proj);

        lstm_layer_persistent<<<NBLK, 256>>>(proj, Whh_l, out_seq, hA, hB, cb);
    }
}

// round 16
// speedup vs baseline: 1.2904x; 1.2904x over previous
#include <cuda_runtime.h>
#include <cuda_bf16.h>
#include <math.h>

// Problem constants
#define BB 64        // batch
#define TT 512       // seq len
#define HH 1024      // hidden (= input size)
#define GG 4096      // 4*H gates
#define LL 3         // layers
#define NBLK 256     // persistent grid size

#define WSTRIDE 1044 // wsa row stride (words): mod 32 = 20 -> 8 consecutive rows cover all banks
#define HSTRIDE 68   // hs row stride

// ---------------- scratch (device globals; no allocation allowed) ----------------
__device__ float g_proj[(size_t)TT * BB * GG];   // [T][B][4H]
__device__ float g_buf0[(size_t)BB * TT * HH];
__device__ float g_buf1[(size_t)BB * TT * HH];
__device__ float g_hA[BB * HH];
__device__ float g_hB[BB * HH];
__device__ float g_c[BB * HH];
__device__ unsigned int g_bar_arrive;
__device__ unsigned int g_bar_gen;

#define FMA2(acc, x, w) \
    asm("fma.rn.f32x2 %0, %1, %2, %0;" : "+l"(acc) : "l"(x), "l"(w))

// ---------------- input-projection GEMM (unchanged from passing R12) ----------------
__global__ void __launch_bounds__(256) xproj_gemm(
    const float* __restrict__ A,
    const float* __restrict__ W,
    const float* __restrict__ bih,
    const float* __restrict__ bhh,
    float* __restrict__ proj)
{
    __shared__ float As[16][128];
    __shared__ float Bs[16][128];

    const int tid = threadIdx.x;
    const int bm = blockIdx.y * 128;
    const int bn = blockIdx.x * 128;
    const int tx = tid & 15;
    const int ty = tid >> 4;

    unsigned long long acc2[8][4];
#pragma unroll
    for (int i = 0; i < 8; i++)
#pragma unroll
        for (int j = 0; j < 4; j++) acc2[i][j] = 0ull;

    const int lr = tid >> 1;
    const int lc = (tid & 1) * 8;
    const float* Ap = A + (size_t)(bm + lr) * HH + lc;
    const float* Wp = W + (size_t)(bn + lr) * HH + lc;

    for (int k = 0; k < HH; k += 16) {
        float4 av0 = *(const float4*)(Ap + k);
        float4 av1 = *(const float4*)(Ap + k + 4);
        float4 wv0 = *(const float4*)(Wp + k);
        float4 wv1 = *(const float4*)(Wp + k + 4);
        __syncthreads();
        As[lc + 0][lr] = av0.x; As[lc + 1][lr] = av0.y;
        As[lc + 2][lr] = av0.z; As[lc + 3][lr] = av0.w;
        As[lc + 4][lr] = av1.x; As[lc + 5][lr] = av1.y;
        As[lc + 6][lr] = av1.z; As[lc + 7][lr] = av1.w;
        Bs[lc + 0][lr] = wv0.x; Bs[lc + 1][lr] = wv0.y;
        Bs[lc + 2][lr] = wv0.z; Bs[lc + 3][lr] = wv0.w;
        Bs[lc + 4][lr] = wv1.x; Bs[lc + 5][lr] = wv1.y;
        Bs[lc + 6][lr] = wv1.z; Bs[lc + 7][lr] = wv1.w;
        __syncthreads();
#pragma unroll
        for (int kk = 0; kk < 16; kk++) {
            float a[8];
            *(float4*)&a[0] = *(const float4*)&As[kk][ty * 8];
            *(float4*)&a[4] = *(const float4*)&As[kk][ty * 8 + 4];
            ulonglong2 b0 = *(const ulonglong2*)&Bs[kk][tx * 8];
            ulonglong2 b1 = *(const ulonglong2*)&Bs[kk][tx * 8 + 4];
#pragma unroll
            for (int i = 0; i < 8; i++) {
                unsigned long long a2;
                asm("mov.b64 %0, {%1, %1};" : "=l"(a2) : "f"(a[i]));
                FMA2(acc2[i][0], a2, b0.x);
                FMA2(acc2[i][1], a2, b0.y);
                FMA2(acc2[i][2], a2, b1.x);
                FMA2(acc2[i][3], a2, b1.y);
            }
        }
    }

#pragma unroll
    for (int i = 0; i < 8; i++) {
        int row = bm + ty * 8 + i;
        int b   = row >> 9;
        int t   = row & 511;
        float* op = proj + ((size_t)(t * BB + b)) * GG + bn + tx * 8;
#pragma unroll
        for (int j2 = 0; j2 < 4; j2++) {
            float lo, hi;
            asm("mov.b64 {%0, %1}, %2;" : "=f"(lo), "=f"(hi) : "l"(acc2[i][j2]));
            int c0 = bn + tx * 8 + 2 * j2;
            op[2 * j2 + 0] = lo + bih[c0]     + bhh[c0];
            op[2 * j2 + 1] = hi + bih[c0 + 1] + bhh[c0 + 1];
        }
    }
}

// ---------------- persistent per-layer LSTM recurrence ----------------
// 256 blocks x 256 threads, block owns 4 h-cols (16 gate cols), M=64.
// 4 groups of 64 threads; each group: 8x2 thread tile over a 16-k quarter of
// each 64-k chunk; partials reduced through smem.  Conflict-free LDS patterns:
//   w: wsa row stride 1044 (mod32=20) -> 8 consecutive rows cover all banks
//   h: rows rg+8i, rg 0..3 consecutive -> banks {0,4,8,12}(+16) per instr
__global__ void __launch_bounds__(256, 2) lstm_layer_persistent(
    const float* __restrict__ proj,     // [T][B][G]
    const float* __restrict__ Whh,      // [G][H]
    float* __restrict__ outseq,         // [B][T][H]
    float* __restrict__ hA,
    float* __restrict__ hB,
    float* __restrict__ cbuf)           // [B][H]
{
    __shared__ float wsa[16][WSTRIDE];  // 66.8 KB  weight slice, resident all layer
    __shared__ float hs[64][HSTRIDE];   // 17.4 KB  h chunk
    __shared__ float part[4][64][17];   // 18.1 KB  per-group partial gates

    const int tid = threadIdx.x;
    const int j0  = blockIdx.x * 4;

    const int grp = tid >> 6;           // 0..3  (k-quarter)
    const int loc = tid & 63;
    const int cg  = loc & 7;            // col-group: cols v=cg and v=cg+8
    const int rg  = loc >> 3;           // 0..7: rows rg+8i, i=0..7

    // ---- load this block's Whh slice into smem ONCE (row v -> gate row gc(v)) ----
    {
        int v   = tid >> 4;             // 0..15
        int c4  = tid & 15;
        int grow = (v >> 2) * HH + j0 + (v & 3);
        const float4* src = (const float4*)(Whh + (size_t)grow * HH);
#pragma unroll
        for (int c = 0; c < 16; c++) {
            int f4 = c * 16 + c4;       // 0..255
            float4 w = src[f4];
            *(float4*)&wsa[v][f4 * 4] = w;
        }
    }
    __syncthreads();

    for (int t = 0; t < TT; t++) {
        unsigned long long acc2[8][2];
#pragma unroll
        for (int i = 0; i < 8; i++) { acc2[i][0] = 0ull; acc2[i][1] = 0ull; }

        if (t > 0) {
            const float* hprev = (t & 1) ? hA : hB;
            for (int c64 = 0; c64 < HH; c64 += 64) {
                // stage h chunk (all 256 threads, coalesced)
#pragma unroll
                for (int it = 0; it < 4; it++) {
                    int idx = tid + it * 256;
                    int m  = idx >> 4;
                    int kq = idx & 15;
                    float4 v4 = *(const float4*)(hprev + (size_t)m * HH + c64 + kq * 4);
                    *(float4*)&hs[m][kq * 4] = v4;
                }
                __syncthreads();
                // group computes its 16-k quarter of this chunk
                int qb = grp * 16;
#pragma unroll
                for (int kk = 0; kk < 16; kk += 4) {
                    int kb = qb + kk;
                    ulonglong2 w0 = *(const ulonglong2*)&wsa[cg    ][c64 + kb];
                    ulonglong2 w1 = *(const ulonglong2*)&wsa[cg + 8][c64 + kb];
#pragma unroll
                    for (int i = 0; i < 8; i++) {
                        ulonglong2 h2 = *(const ulonglong2*)&hs[rg + 8 * i][kb];
                        FMA2(acc2[i][0], h2.x, w0.x);
                        FMA2(acc2[i][0], h2.y, w0.y);
                        FMA2(acc2[i][1], h2.x, w1.x);
                        FMA2(acc2[i][1], h2.y, w1.y);
                    }
                }
                __syncthreads();
            }
            // write group partials (pair-summed)
#pragma unroll
            for (int i = 0; i < 8; i++) {
                float lo, hi;
                asm("mov.b64 {%0, %1}, %2;" : "=f"(lo), "=f"(hi) : "l"(acc2[i][0]));
                part[grp][rg + 8 * i][cg]     = lo + hi;
                asm("mov.b64 {%0, %1}, %2;" : "=f"(lo), "=f"(hi) : "l"(acc2[i][1]));
                part[grp][rg + 8 * i][cg + 8] = lo + hi;
            }
        }
        __syncthreads();

        // gates: one (m, j) h-output per thread
        float* hcur = (t & 1) ? hB : hA;
        {
            int m  = tid >> 2;
            int j2 = tid & 3;
            const float* pr = proj + ((size_t)t * BB + m) * GG + j0 + j2;
            float ig = pr[0 * HH];
            float fg = pr[1 * HH];
            float gg = pr[2 * HH];
            float og = pr[3 * HH];
            if (t > 0) {
#pragma unroll
                for (int g = 0; g < 4; g++) {
                    ig += part[g][m][j2];
                    fg += part[g][m][4  + j2];
                    gg += part[g][m][8  + j2];
                    og += part[g][m][12 + j2];
                }
            }
            ig = 1.f / (1.f + expf(-ig));
            fg = 1.f / (1.f + expf(-fg));
            og = 1.f / (1.f + expf(-og));
            gg = tanhf(gg);
            int j = j0 + j2;
            float cp = (t == 0) ? 0.f : cbuf[(size_t)m * HH + j];
            float c  = fg * cp + ig * gg;
            cbuf[(size_t)m * HH + j] = c;
            float h = og * tanhf(c);
            hcur[(size_t)m * HH + j] = h;
            outseq[((size_t)m * TT + t) * HH + j] = h;
        }

        // ---- grid-wide barrier between timesteps ----
        __syncthreads();
        __threadfence();
        if (tid == 0) {
            unsigned int gen = atomicAdd(&g_bar_gen, 0u);
            __threadfence();
            unsigned int ticket = atomicAdd(&g_bar_arrive, 1u);
            if (ticket == (unsigned int)(gridDim.x - 1)) {
                g_bar_arrive = 0;
                __threadfence();
                atomicAdd(&g_bar_gen, 1u);
            } else {
                while (*(volatile unsigned int*)&g_bar_gen == gen) {
                    __nanosleep(64);
                }
            }
            __threadfence();
        }
        __syncthreads();
    }
}

// ---------------- launch: 6 graph nodes ----------------
extern "C" void kernel_launch(void* const* d_in, const int* in_sizes, int n_in,
                              void* d_out, int out_size)
{
    (void)in_sizes; (void)n_in; (void)out_size;
    const float* x   = (const float*)d_in[0];
    const float* Wih = (const float*)d_in[1];
    const float* Whh = (const float*)d_in[2];
    const float* bih = (const float*)d_in[3];
    const float* bhh = (const float*)d_in[4];
    float* out = (float*)d_out;

    float *proj, *buf0, *buf1, *hA, *hB, *cb;
    cudaGetSymbolAddress((void**)&proj, g_proj);
    cudaGetSymbolAddress((void**)&buf0, g_buf0);
    cudaGetSymbolAddress((void**)&buf1, g_buf1);
    cudaGetSymbolAddress((void**)&hA,   g_hA);
    cudaGetSymbolAddress((void**)&hB,   g_hB);
    cudaGetSymbolAddress((void**)&cb,   g_c);

    for (int l = 0; l < LL; l++) {
        const float* in_seq  = (l == 0) ? x    : ((l == 1) ? buf0 : buf1);
        float*       out_seq = (l == 0) ? buf0 : ((l == 1) ? buf1 : out);
        const float* Wih_l = Wih + (size_t)l * GG * HH;
        const float* Whh_l = Whh + (size_t)l * GG * HH;
        const float* bih_l = bih + (size_t)l * GG;
        const float* bhh_l = bhh + (size_t)l * GG;

        dim3 ggrid(GG / 128, (BB * TT) / 128);   // (32, 256)
        xproj_gemm<<<ggrid, 256>>>(in_seq, Wih_l, bih_l, bhh_l, proj);

        lstm_layer_persistent<<<NBLK, 256>>>(proj, Whh_l, out_seq, hA, hB, cb);
    }
}